// round 1
// baseline (speedup 1.0000x reference)
#include <cuda_runtime.h>
#include <cstdint>

#define BB 64
#define TT 1024
#define II 128
#define HH 256

// y1 scratch: [B, T, H] fp32 = 64 MB (static __device__ to satisfy alloc rules)
__device__ float g_y1[BB * TT * HH];

// ---------------------------------------------------------------- helpers
__device__ __forceinline__ uint32_t smem_u32(const void* p) {
    uint32_t a;
    asm("{ .reg .u64 t; cvta.to.shared.u64 t, %1; cvt.u32.u64 %0, t; }"
        : "=r"(a) : "l"(p));
    return a;
}
__device__ __forceinline__ void st_remote_f32(uint32_t local_addr, uint32_t rank, float v) {
    uint32_t ra;
    asm volatile("mapa.shared::cluster.u32 %0, %1, %2;" : "=r"(ra) : "r"(local_addr), "r"(rank));
    asm volatile("st.shared::cluster.f32 [%0], %1;" :: "r"(ra), "f"(v));
}
__device__ __forceinline__ void cluster_sync_() {
    asm volatile("barrier.cluster.arrive.aligned;" ::: "memory");
    asm volatile("barrier.cluster.wait.aligned;" ::: "memory");
}
__device__ __forceinline__ float sigmoidf_(float z) {
    return 1.0f / (1.0f + __expf(-z));
}

// ================================================================ PASS 1
// Layer 1: cluster of 4 CTAs, 2 batch rows per cluster.
// Each CTA owns 64 j-columns x 2 gates = 128 gate-cols, K = 384 (x:128 | h:256).
// 256 threads: u = tid&127 -> gate-col, ks = tid>>7 -> K-split half (192 each).

struct P1Smem {
    float4 w4[96 * 128];        // [k4][gcol] : 196608 B
    float  comb[2][2][384];     // double-buffered [x_t | h] per row : 6144 B
    float  partial[256][2];     // k-split partials : 2048 B
    float  gates[2][2][64];     // [gate][row][jl] : 1024 B
    float  bias[128];           // 512 B
};                              // total 206336 B

__global__ void __cluster_dims__(4, 1, 1) __launch_bounds__(256, 1)
mgu_pass1(const float* __restrict__ x,
          const float* __restrict__ Wf1, const float* __restrict__ bf1,
          const float* __restrict__ Wc1, const float* __restrict__ bc1,
          float* __restrict__ out)
{
    extern __shared__ char raw[];
    P1Smem* s = reinterpret_cast<P1Smem*>(raw);

    const int tid  = threadIdx.x;
    const int rank = blockIdx.x & 3;
    const int cid  = blockIdx.x >> 2;
    const int b0   = cid * 2;

    const int u    = tid & 127;
    const int ks   = tid >> 7;       // 0..1
    const int gate = u >> 6;         // 0=f, 1=c
    const int jl   = u & 63;
    const int j0   = rank * 64;

    // ---- load weights into SMEM, layout w4[k>>2][gcol].comp[k&3] = W[k][j0 + (g&63)]
    for (int idx = tid; idx < 128 * 384; idx += 256) {
        int k = idx >> 7;            // 0..383 (concat row: x rows 0..127, h rows 128..383)
        int g = idx & 127;
        const float* W = (g >> 6) ? Wc1 : Wf1;
        float w = W[k * HH + ((g & 63) + j0)];
        reinterpret_cast<float*>(&s->w4[(k >> 2) * 128 + g])[k & 3] = w;
    }
    if (tid < 128) s->bias[tid] = ((tid >> 6) ? bc1 : bf1)[(tid & 63) + j0];

    // ---- comb[0] init: x(t=0) | h=0
    for (int idx = tid; idx < 2 * 384; idx += 256) {
        int row = idx / 384, k = idx % 384;
        s->comb[0][row][k] = (k < II) ? x[(b0 + row) * (TT * II) + k] : 0.0f;
    }
    __syncthreads();
    cluster_sync_();

    const float4* wbase = &s->w4[ks * 48 * 128 + u];
    const int prow = tid >> 5, pch = tid & 31;   // x-prefetch mapping (tid < 64)

    for (int t = 0; t < TT; ++t) {
        const int cur = t & 1, nxt = cur ^ 1;

        // prefetch x(t+1) into regs (latency hidden under dot)
        float4 xv = make_float4(0.f, 0.f, 0.f, 0.f);
        if (tid < 64 && t + 1 < TT)
            xv = *reinterpret_cast<const float4*>(
                &x[(b0 + prow) * (TT * II) + (t + 1) * II + pch * 4]);

        // ---- dot: acc over this thread's 192-K half for both rows
        const float4* c0 = reinterpret_cast<const float4*>(&s->comb[cur][0][ks * 192]);
        const float4* c1 = reinterpret_cast<const float4*>(&s->comb[cur][1][ks * 192]);
        float a0 = 0.f, a1 = 0.f;
        #pragma unroll 8
        for (int q = 0; q < 48; ++q) {
            float4 w  = wbase[q * 128];
            float4 v0 = c0[q];
            float4 v1 = c1[q];
            a0 = fmaf(w.x, v0.x, a0); a0 = fmaf(w.y, v0.y, a0);
            a0 = fmaf(w.z, v0.z, a0); a0 = fmaf(w.w, v0.w, a0);
            a1 = fmaf(w.x, v1.x, a1); a1 = fmaf(w.y, v1.y, a1);
            a1 = fmaf(w.z, v1.z, a1); a1 = fmaf(w.w, v1.w, a1);
        }
        s->partial[tid][0] = a0;
        s->partial[tid][1] = a1;
        __syncthreads();

        // ---- k-split reduce + activation (tid<128 have ks==0)
        if (tid < 128) {
            float p0 = a0 + s->partial[tid + 128][0] + s->bias[tid];
            float p1 = a1 + s->partial[tid + 128][1] + s->bias[tid];
            float g0, g1;
            if (gate == 0) { g0 = sigmoidf_(p0); g1 = sigmoidf_(p1); }
            else           { g0 = tanhf(p0);    g1 = tanhf(p1);    }
            s->gates[gate][0][jl] = g0;
            s->gates[gate][1][jl] = g1;
        }
        __syncthreads();

        // ---- h update + DSMEM broadcast of this CTA's 64-j slice
        if (tid < 128) {
            const int row = tid >> 6, j2 = tid & 63;
            const int jg = j0 + j2;
            float f    = s->gates[0][row][j2];
            float c    = s->gates[1][row][j2];
            float hold = s->comb[cur][row][II + jg];
            float hn   = fmaf(f, hold - c, c);   // f*h + (1-f)*c

            g_y1[(b0 + row) * (TT * HH) + t * HH + jg] = hn;
            if (t == TT - 1)
                out[BB * TT * HH + (b0 + row) * HH + jg] = hn;   // hidden layer 0

            uint32_t la = smem_u32(&s->comb[nxt][row][II + jg]);
            #pragma unroll
            for (int p = 0; p < 4; ++p) st_remote_f32(la, (uint32_t)p, hn);
        }
        // stage prefetched x into comb[nxt] x-section
        if (tid < 64 && t + 1 < TT)
            *reinterpret_cast<float4*>(&s->comb[nxt][prow][pch * 4]) = xv;

        cluster_sync_();
    }
}

// ================================================================ PASS 2
// Layer 2: cluster of 8 CTAs, 4 batch rows per cluster.
// Each CTA owns 32 j-columns x 2 gates = 64 gate-cols, K = 512 (y1:256 | h2:256).
// 256 threads: u = tid&63 -> gate-col, ks = tid>>6 -> K-split quarter (128 each).

struct P2Smem {
    float4 w4[128 * 64];        // 131072 B
    float  comb[2][4][512];     // 16384 B
    float  partial[256][4];     // 4096 B
    float  gates[2][4][32];     // 1024 B
    float  bias[64];            // 256 B
};                              // total 152832 B

__global__ void __cluster_dims__(8, 1, 1) __launch_bounds__(256, 1)
mgu_pass2(const float* __restrict__ Wf2, const float* __restrict__ bf2,
          const float* __restrict__ Wc2, const float* __restrict__ bc2,
          float* __restrict__ out)
{
    extern __shared__ char raw[];
    P2Smem* s = reinterpret_cast<P2Smem*>(raw);

    const int tid  = threadIdx.x;
    const int rank = blockIdx.x & 7;
    const int cid  = blockIdx.x >> 3;
    const int b0   = cid * 4;

    const int u    = tid & 63;
    const int ks   = tid >> 6;       // 0..3
    const int gate = u >> 5;
    const int jl   = u & 31;
    const int j0   = rank * 32;

    // ---- weights
    for (int idx = tid; idx < 64 * 512; idx += 256) {
        int k = idx >> 6;            // 0..511 (y1 rows 0..255, h rows 256..511)
        int g = idx & 63;
        const float* W = (g >> 5) ? Wc2 : Wf2;
        float w = W[k * HH + ((g & 31) + j0)];
        reinterpret_cast<float*>(&s->w4[(k >> 2) * 64 + g])[k & 3] = w;
    }
    if (tid < 64) s->bias[tid] = ((tid >> 5) ? bc2 : bf2)[(tid & 31) + j0];

    // ---- comb[0] init: y1(t=0) | h2=0
    for (int idx = tid; idx < 4 * 512; idx += 256) {
        int row = idx / 512, k = idx % 512;
        s->comb[0][row][k] = (k < HH) ? g_y1[(b0 + row) * (TT * HH) + k] : 0.0f;
    }
    __syncthreads();
    cluster_sync_();

    const float4* wbase = &s->w4[ks * 32 * 64 + u];
    const int prow = tid >> 6, pch = tid & 63;   // y1-prefetch mapping (all 256 threads)

    for (int t = 0; t < TT; ++t) {
        const int cur = t & 1, nxt = cur ^ 1;

        float4 yv = make_float4(0.f, 0.f, 0.f, 0.f);
        if (t + 1 < TT)
            yv = *reinterpret_cast<const float4*>(
                &g_y1[(b0 + prow) * (TT * HH) + (t + 1) * HH + pch * 4]);

        const float4* c0 = reinterpret_cast<const float4*>(&s->comb[cur][0][ks * 128]);
        const float4* c1 = reinterpret_cast<const float4*>(&s->comb[cur][1][ks * 128]);
        const float4* c2 = reinterpret_cast<const float4*>(&s->comb[cur][2][ks * 128]);
        const float4* c3 = reinterpret_cast<const float4*>(&s->comb[cur][3][ks * 128]);
        float a0 = 0.f, a1 = 0.f, a2 = 0.f, a3 = 0.f;
        #pragma unroll 8
        for (int q = 0; q < 32; ++q) {
            float4 w  = wbase[q * 64];
            float4 v0 = c0[q]; float4 v1 = c1[q];
            float4 v2 = c2[q]; float4 v3 = c3[q];
            a0 = fmaf(w.x, v0.x, a0); a0 = fmaf(w.y, v0.y, a0);
            a0 = fmaf(w.z, v0.z, a0); a0 = fmaf(w.w, v0.w, a0);
            a1 = fmaf(w.x, v1.x, a1); a1 = fmaf(w.y, v1.y, a1);
            a1 = fmaf(w.z, v1.z, a1); a1 = fmaf(w.w, v1.w, a1);
            a2 = fmaf(w.x, v2.x, a2); a2 = fmaf(w.y, v2.y, a2);
            a2 = fmaf(w.z, v2.z, a2); a2 = fmaf(w.w, v2.w, a2);
            a3 = fmaf(w.x, v3.x, a3); a3 = fmaf(w.y, v3.y, a3);
            a3 = fmaf(w.z, v3.z, a3); a3 = fmaf(w.w, v3.w, a3);
        }
        *reinterpret_cast<float4*>(&s->partial[tid][0]) = make_float4(a0, a1, a2, a3);
        __syncthreads();

        if (tid < 64) {               // ks==0 threads
            float p0 = a0, p1 = a1, p2 = a2, p3 = a3;
            #pragma unroll
            for (int q4 = 1; q4 < 4; ++q4) {
                p0 += s->partial[tid + 64 * q4][0];
                p1 += s->partial[tid + 64 * q4][1];
                p2 += s->partial[tid + 64 * q4][2];
                p3 += s->partial[tid + 64 * q4][3];
            }
            float b = s->bias[tid];
            p0 += b; p1 += b; p2 += b; p3 += b;
            float g0, g1, g2, g3;
            if (gate == 0) {
                g0 = sigmoidf_(p0); g1 = sigmoidf_(p1);
                g2 = sigmoidf_(p2); g3 = sigmoidf_(p3);
            } else {
                g0 = tanhf(p0); g1 = tanhf(p1);
                g2 = tanhf(p2); g3 = tanhf(p3);
            }
            s->gates[gate][0][jl] = g0;
            s->gates[gate][1][jl] = g1;
            s->gates[gate][2][jl] = g2;
            s->gates[gate][3][jl] = g3;
        }
        __syncthreads();

        if (tid < 128) {
            const int row = tid >> 5, j2 = tid & 31;
            const int jg = j0 + j2;
            float f    = s->gates[0][row][j2];
            float c    = s->gates[1][row][j2];
            float hold = s->comb[cur][row][HH + jg];
            float hn   = fmaf(f, hold - c, c);

            out[(b0 + row) * (TT * HH) + t * HH + jg] = hn;          // y2
            if (t == TT - 1)
                out[BB * TT * HH + BB * HH + (b0 + row) * HH + jg] = hn;  // hidden layer 1

            uint32_t la = smem_u32(&s->comb[nxt][row][HH + jg]);
            #pragma unroll
            for (int p = 0; p < 8; ++p) st_remote_f32(la, (uint32_t)p, hn);
        }
        if (t + 1 < TT)
            *reinterpret_cast<float4*>(&s->comb[nxt][prow][pch * 4]) = yv;

        cluster_sync_();
    }
}

// ================================================================ launch
extern "C" void kernel_launch(void* const* d_in, const int* in_sizes, int n_in,
                              void* d_out, int out_size)
{
    (void)in_sizes; (void)n_in; (void)out_size;
    const float* x   = (const float*)d_in[0];
    const float* Wf1 = (const float*)d_in[1];
    const float* bf1 = (const float*)d_in[2];
    const float* Wc1 = (const float*)d_in[3];
    const float* bc1 = (const float*)d_in[4];
    const float* Wf2 = (const float*)d_in[5];
    const float* bf2 = (const float*)d_in[6];
    const float* Wc2 = (const float*)d_in[7];
    const float* bc2 = (const float*)d_in[8];
    float* out = (float*)d_out;

    cudaFuncSetAttribute(mgu_pass1, cudaFuncAttributeMaxDynamicSharedMemorySize,
                         (int)sizeof(P1Smem));
    cudaFuncSetAttribute(mgu_pass2, cudaFuncAttributeMaxDynamicSharedMemorySize,
                         (int)sizeof(P2Smem));

    mgu_pass1<<<128, 256, sizeof(P1Smem)>>>(x, Wf1, bf1, Wc1, bc1, out);
    mgu_pass2<<<128, 256, sizeof(P2Smem)>>>(Wf2, bf2, Wc2, bc2, out);
}

// round 3
// speedup vs baseline: 2.1183x; 2.1183x over previous
#include <cuda_runtime.h>
#include <cstdint>

#define BB 64
#define TT 1024
#define II 128
#define HH 256

// y1 scratch: [B, T, H] fp32 = 64 MB
__device__ float g_y1[BB * TT * HH];

// ---------------------------------------------------------------- helpers
__device__ __forceinline__ uint32_t smem_u32(const void* p) {
    uint32_t a;
    asm("{ .reg .u64 t; cvta.to.shared.u64 t, %1; cvt.u32.u64 %0, t; }"
        : "=r"(a) : "l"(p));
    return a;
}
__device__ __forceinline__ void st_remote_f32(uint32_t local_addr, uint32_t rank, float v) {
    uint32_t ra;
    asm volatile("mapa.shared::cluster.u32 %0, %1, %2;" : "=r"(ra) : "r"(local_addr), "r"(rank));
    asm volatile("st.shared::cluster.f32 [%0], %1;" :: "r"(ra), "f"(v));
}
__device__ __forceinline__ void cluster_sync_() {
    asm volatile("barrier.cluster.arrive.aligned;" ::: "memory");
    asm volatile("barrier.cluster.wait.aligned;" ::: "memory");
}
#define CLUSTER_ARRIVE() asm volatile("barrier.cluster.arrive.aligned;" ::: "memory")
#define CLUSTER_WAIT()   asm volatile("barrier.cluster.wait.aligned;" ::: "memory")

__device__ __forceinline__ float sigmoid_(float z) {
    return __fdividef(1.0f, 1.0f + __expf(-z));
}
__device__ __forceinline__ float tanh_(float z) {
    return __fdividef(2.0f, 1.0f + __expf(-2.0f * z)) - 1.0f;
}

// ================================================================ PASS 1
// Layer 1: cluster of 4 CTAs, 2 batch rows per cluster.
// CTA owns 64 j-columns (BOTH gates), K = 384 (x:128 | h:256).
// 256 threads = j(64) x ks(4). Thread k-slice: k4 = q*4 + ks, q=0..23.
//   q<8  -> k4<32  -> x region (h-independent: runs before cluster wait)
//   q>=8 -> h region.
// Barrier protocol per step: [dot-A(x)] WAIT [dot-B(h)] sync [reduce/update/
// remote-store] ARRIVE — the wait is hidden under dot-A of the same step, the
// arrive of step t is consumed by waits at step t+1. Final WAIT after the loop
// keeps every CTA alive until all in-flight remote stores have landed.

struct P1Smem {
    float4 w4[2][96][64];      // [gate][k4][j] : 196608 B
    float  comb[2][2][384];    // double-buffered [x_t | h] per row : 6144 B
    float4 partial[256];       // (af0, ac0, af1, ac1) : 4096 B
    float  biasf[64];
    float  biasc[64];          // 512 B
};                             // 207360 B

__global__ void __cluster_dims__(4, 1, 1) __launch_bounds__(256, 1)
mgu_pass1(const float* __restrict__ x,
          const float* __restrict__ Wf1, const float* __restrict__ bf1,
          const float* __restrict__ Wc1, const float* __restrict__ bc1,
          float* __restrict__ out)
{
    extern __shared__ char raw[];
    P1Smem* s = reinterpret_cast<P1Smem*>(raw);

    const int tid  = threadIdx.x;
    const int rank = blockIdx.x & 3;
    const int cid  = blockIdx.x >> 2;
    const int b0   = cid * 2;
    const int j    = tid & 63;
    const int ks   = tid >> 6;        // 0..3
    const int j0   = rank * 64;

    // ---- weights: w4[gate][k>>2][j].comp[k&3]
    for (int idx = tid; idx < 384 * 64; idx += 256) {
        int k = idx >> 6, jj = idx & 63;
        reinterpret_cast<float*>(&s->w4[0][k >> 2][jj])[k & 3] = Wf1[k * HH + j0 + jj];
        reinterpret_cast<float*>(&s->w4[1][k >> 2][jj])[k & 3] = Wc1[k * HH + j0 + jj];
    }
    if (tid < 64) { s->biasf[tid] = bf1[j0 + tid]; s->biasc[tid] = bc1[j0 + tid]; }

    // ---- comb init: zero both buffers, then x(0)
    for (int idx = tid; idx < 2 * 2 * 384; idx += 256)
        reinterpret_cast<float*>(s->comb)[idx] = 0.0f;
    __syncthreads();
    if (tid < 64) {
        int row = tid >> 5, ch = tid & 31;
        reinterpret_cast<float4*>(&s->comb[0][row][0])[ch] =
            reinterpret_cast<const float4*>(&x[(b0 + row) * (TT * II)])[ch];
    }
    __syncthreads();
    cluster_sync_();

    const int prow = tid >> 5, pch = tid & 31;   // x-prefetch mapping (tid < 64)

    for (int t = 0; t < TT; ++t) {
        const int cur = t & 1, nxt = cur ^ 1;

        // prefetch x(t+1) (DRAM latency hidden under the dot)
        float4 xv = make_float4(0.f, 0.f, 0.f, 0.f);
        if (tid < 64 && t + 1 < TT)
            xv = *reinterpret_cast<const float4*>(
                &x[(b0 + prow) * (TT * II) + (t + 1) * II + pch * 4]);

        const float4* cb0 = reinterpret_cast<const float4*>(s->comb[cur][0]);
        const float4* cb1 = reinterpret_cast<const float4*>(s->comb[cur][1]);
        float af0 = 0.f, ac0 = 0.f, af1 = 0.f, ac1 = 0.f;

        // ---- A: x-portion (independent of h(t)) — hides the cluster wait
        #pragma unroll
        for (int q = 0; q < 8; ++q) {
            const int k4 = q * 4 + ks;
            float4 w0 = s->w4[0][k4][j];
            float4 w1 = s->w4[1][k4][j];
            float4 v0 = cb0[k4];
            float4 v1 = cb1[k4];
            af0 = fmaf(w0.x, v0.x, af0); af0 = fmaf(w0.y, v0.y, af0);
            af0 = fmaf(w0.z, v0.z, af0); af0 = fmaf(w0.w, v0.w, af0);
            ac0 = fmaf(w1.x, v0.x, ac0); ac0 = fmaf(w1.y, v0.y, ac0);
            ac0 = fmaf(w1.z, v0.z, ac0); ac0 = fmaf(w1.w, v0.w, ac0);
            af1 = fmaf(w0.x, v1.x, af1); af1 = fmaf(w0.y, v1.y, af1);
            af1 = fmaf(w0.z, v1.z, af1); af1 = fmaf(w0.w, v1.w, af1);
            ac1 = fmaf(w1.x, v1.x, ac1); ac1 = fmaf(w1.y, v1.y, ac1);
            ac1 = fmaf(w1.z, v1.z, ac1); ac1 = fmaf(w1.w, v1.w, ac1);
        }

        if (t) CLUSTER_WAIT();   // h(t) now visible in comb[cur] h-region

        // ---- B: h-portion
        #pragma unroll
        for (int q = 8; q < 24; ++q) {
            const int k4 = q * 4 + ks;
            float4 w0 = s->w4[0][k4][j];
            float4 w1 = s->w4[1][k4][j];
            float4 v0 = cb0[k4];
            float4 v1 = cb1[k4];
            af0 = fmaf(w0.x, v0.x, af0); af0 = fmaf(w0.y, v0.y, af0);
            af0 = fmaf(w0.z, v0.z, af0); af0 = fmaf(w0.w, v0.w, af0);
            ac0 = fmaf(w1.x, v0.x, ac0); ac0 = fmaf(w1.y, v0.y, ac0);
            ac0 = fmaf(w1.z, v0.z, ac0); ac0 = fmaf(w1.w, v0.w, ac0);
            af1 = fmaf(w0.x, v1.x, af1); af1 = fmaf(w0.y, v1.y, af1);
            af1 = fmaf(w0.z, v1.z, af1); af1 = fmaf(w0.w, v1.w, af1);
            ac1 = fmaf(w1.x, v1.x, ac1); ac1 = fmaf(w1.y, v1.y, ac1);
            ac1 = fmaf(w1.z, v1.z, ac1); ac1 = fmaf(w1.w, v1.w, ac1);
        }

        // stage x(t+1) (different buffer than anything being read this step)
        if (tid < 64 && t + 1 < TT)
            reinterpret_cast<float4*>(&s->comb[nxt][prow][0])[pch] = xv;

        s->partial[tid] = make_float4(af0, ac0, af1, ac1);
        __syncthreads();

        // ---- D: reduce + activations + h update + DSMEM broadcast (one phase)
        if (tid < 128) {
            const int row = tid >> 6, jl = tid & 63;
            float4 p0 = s->partial[jl];
            float4 p1 = s->partial[64 + jl];
            float4 p2 = s->partial[128 + jl];
            float4 p3 = s->partial[192 + jl];
            float pf, pc;
            if (row == 0) { pf = (p0.x + p1.x) + (p2.x + p3.x);
                            pc = (p0.y + p1.y) + (p2.y + p3.y); }
            else          { pf = (p0.z + p1.z) + (p2.z + p3.z);
                            pc = (p0.w + p1.w) + (p2.w + p3.w); }
            pf += s->biasf[jl];
            pc += s->biasc[jl];
            float f = sigmoid_(pf);
            float c = tanh_(pc);
            const int jg = j0 + jl;
            float hold = s->comb[cur][row][II + jg];
            float hn   = fmaf(f, hold - c, c);     // f*h + (1-f)*c

            g_y1[(b0 + row) * (TT * HH) + t * HH + jg] = hn;
            if (t == TT - 1)
                out[BB * TT * HH + (b0 + row) * HH + jg] = hn;   // hidden layer 0

            uint32_t la = smem_u32(&s->comb[nxt][row][II + jg]);
            #pragma unroll
            for (int p = 0; p < 4; ++p) st_remote_f32(la, (uint32_t)p, hn);
        }
        CLUSTER_ARRIVE();   // releases this step's remote stores; hidden under next dot-A
    }
    CLUSTER_WAIT();   // exit protection: no CTA leaves while peer stores are in flight
}

// ================================================================ PASS 2
// Layer 2: cluster of 8 CTAs, 4 batch rows per cluster.
// CTA owns 32 j-columns (BOTH gates), K = 512 (y1:256 | h:256).
// 256 threads = j(32) x ks(8). Thread k-slice: k4 = q*8 + ks, q=0..15.
//   q<8  -> k4<64  -> y1 region (h-independent)
//   q>=8 -> h region.

struct P2Smem {
    float4 w4[2][128][32];     // 131072 B
    float  comb[2][4][512];    // 16384 B
    float  partial[256][8];    // af[4] | ac[4] : 8192 B
    float  biasf[32];
    float  biasc[32];          // 256 B
};                             // 155904 B

__global__ void __cluster_dims__(8, 1, 1) __launch_bounds__(256, 1)
mgu_pass2(const float* __restrict__ Wf2, const float* __restrict__ bf2,
          const float* __restrict__ Wc2, const float* __restrict__ bc2,
          float* __restrict__ out)
{
    extern __shared__ char raw[];
    P2Smem* s = reinterpret_cast<P2Smem*>(raw);

    const int tid  = threadIdx.x;
    const int rank = blockIdx.x & 7;
    const int cid  = blockIdx.x >> 3;
    const int b0   = cid * 4;
    const int j    = tid & 31;
    const int ks   = tid >> 5;        // 0..7
    const int j0   = rank * 32;

    // ---- weights
    for (int idx = tid; idx < 512 * 32; idx += 256) {
        int k = idx >> 5, jj = idx & 31;
        reinterpret_cast<float*>(&s->w4[0][k >> 2][jj])[k & 3] = Wf2[k * HH + j0 + jj];
        reinterpret_cast<float*>(&s->w4[1][k >> 2][jj])[k & 3] = Wc2[k * HH + j0 + jj];
    }
    if (tid < 32) { s->biasf[tid] = bf2[j0 + tid]; s->biasc[tid] = bc2[j0 + tid]; }

    for (int idx = tid; idx < 2 * 4 * 512; idx += 256)
        reinterpret_cast<float*>(s->comb)[idx] = 0.0f;
    __syncthreads();
    {
        int row = tid >> 6, ch = tid & 63;    // all 256 threads: 4 rows x 64 float4
        reinterpret_cast<float4*>(&s->comb[0][row][0])[ch] =
            reinterpret_cast<const float4*>(&g_y1[(b0 + row) * (TT * HH)])[ch];
    }
    __syncthreads();
    cluster_sync_();

    const int prow = tid >> 6, pch = tid & 63;

    for (int t = 0; t < TT; ++t) {
        const int cur = t & 1, nxt = cur ^ 1;

        float4 yv = make_float4(0.f, 0.f, 0.f, 0.f);
        if (t + 1 < TT)
            yv = *reinterpret_cast<const float4*>(
                &g_y1[(b0 + prow) * (TT * HH) + (t + 1) * HH + pch * 4]);

        const float4* cb0 = reinterpret_cast<const float4*>(s->comb[cur][0]);
        const float4* cb1 = reinterpret_cast<const float4*>(s->comb[cur][1]);
        const float4* cb2 = reinterpret_cast<const float4*>(s->comb[cur][2]);
        const float4* cb3 = reinterpret_cast<const float4*>(s->comb[cur][3]);
        float af0 = 0.f, af1 = 0.f, af2 = 0.f, af3 = 0.f;
        float ac0 = 0.f, ac1 = 0.f, ac2 = 0.f, ac3 = 0.f;

        #pragma unroll
        for (int q = 0; q < 8; ++q) {          // A: y1 region
            const int k4 = q * 8 + ks;
            float4 w0 = s->w4[0][k4][j];
            float4 w1 = s->w4[1][k4][j];
            float4 v;
            v = cb0[k4];
            af0 = fmaf(w0.x, v.x, af0); af0 = fmaf(w0.y, v.y, af0);
            af0 = fmaf(w0.z, v.z, af0); af0 = fmaf(w0.w, v.w, af0);
            ac0 = fmaf(w1.x, v.x, ac0); ac0 = fmaf(w1.y, v.y, ac0);
            ac0 = fmaf(w1.z, v.z, ac0); ac0 = fmaf(w1.w, v.w, ac0);
            v = cb1[k4];
            af1 = fmaf(w0.x, v.x, af1); af1 = fmaf(w0.y, v.y, af1);
            af1 = fmaf(w0.z, v.z, af1); af1 = fmaf(w0.w, v.w, af1);
            ac1 = fmaf(w1.x, v.x, ac1); ac1 = fmaf(w1.y, v.y, ac1);
            ac1 = fmaf(w1.z, v.z, ac1); ac1 = fmaf(w1.w, v.w, ac1);
            v = cb2[k4];
            af2 = fmaf(w0.x, v.x, af2); af2 = fmaf(w0.y, v.y, af2);
            af2 = fmaf(w0.z, v.z, af2); af2 = fmaf(w0.w, v.w, af2);
            ac2 = fmaf(w1.x, v.x, ac2); ac2 = fmaf(w1.y, v.y, ac2);
            ac2 = fmaf(w1.z, v.z, ac2); ac2 = fmaf(w1.w, v.w, ac2);
            v = cb3[k4];
            af3 = fmaf(w0.x, v.x, af3); af3 = fmaf(w0.y, v.y, af3);
            af3 = fmaf(w0.z, v.z, af3); af3 = fmaf(w0.w, v.w, af3);
            ac3 = fmaf(w1.x, v.x, ac3); ac3 = fmaf(w1.y, v.y, ac3);
            ac3 = fmaf(w1.w, v.w, ac3); ac3 = fmaf(w1.z, v.z, ac3);
        }

        if (t) CLUSTER_WAIT();

        #pragma unroll
        for (int q = 8; q < 16; ++q) {         // B: h region
            const int k4 = q * 8 + ks;
            float4 w0 = s->w4[0][k4][j];
            float4 w1 = s->w4[1][k4][j];
            float4 v;
            v = cb0[k4];
            af0 = fmaf(w0.x, v.x, af0); af0 = fmaf(w0.y, v.y, af0);
            af0 = fmaf(w0.z, v.z, af0); af0 = fmaf(w0.w, v.w, af0);
            ac0 = fmaf(w1.x, v.x, ac0); ac0 = fmaf(w1.y, v.y, ac0);
            ac0 = fmaf(w1.z, v.z, ac0); ac0 = fmaf(w1.w, v.w, ac0);
            v = cb1[k4];
            af1 = fmaf(w0.x, v.x, af1); af1 = fmaf(w0.y, v.y, af1);
            af1 = fmaf(w0.z, v.z, af1); af1 = fmaf(w0.w, v.w, af1);
            ac1 = fmaf(w1.x, v.x, ac1); ac1 = fmaf(w1.y, v.y, ac1);
            ac1 = fmaf(w1.z, v.z, ac1); ac1 = fmaf(w1.w, v.w, ac1);
            v = cb2[k4];
            af2 = fmaf(w0.x, v.x, af2); af2 = fmaf(w0.y, v.y, af2);
            af2 = fmaf(w0.z, v.z, af2); af2 = fmaf(w0.w, v.w, af2);
            ac2 = fmaf(w1.x, v.x, ac2); ac2 = fmaf(w1.y, v.y, ac2);
            ac2 = fmaf(w1.z, v.z, ac2); ac2 = fmaf(w1.w, v.w, ac2);
            v = cb3[k4];
            af3 = fmaf(w0.x, v.x, af3); af3 = fmaf(w0.y, v.y, af3);
            af3 = fmaf(w0.z, v.z, af3); af3 = fmaf(w0.w, v.w, af3);
            ac3 = fmaf(w1.x, v.x, ac3); ac3 = fmaf(w1.y, v.y, ac3);
            ac3 = fmaf(w1.z, v.z, ac3); ac3 = fmaf(w1.w, v.w, ac3);
        }

        if (t + 1 < TT)
            reinterpret_cast<float4*>(&s->comb[nxt][prow][0])[pch] = yv;

        reinterpret_cast<float4*>(s->partial[tid])[0] = make_float4(af0, af1, af2, af3);
        reinterpret_cast<float4*>(s->partial[tid])[1] = make_float4(ac0, ac1, ac2, ac3);
        __syncthreads();

        if (tid < 128) {
            const int row = tid >> 5, jl = tid & 31;
            float pf = s->biasf[jl], pc = s->biasc[jl];
            #pragma unroll
            for (int kk = 0; kk < 8; ++kk) {
                pf += s->partial[kk * 32 + jl][row];
                pc += s->partial[kk * 32 + jl][4 + row];
            }
            float f = sigmoid_(pf);
            float c = tanh_(pc);
            const int jg = j0 + jl;
            float hold = s->comb[cur][row][HH + jg];
            float hn   = fmaf(f, hold - c, c);

            out[(b0 + row) * (TT * HH) + t * HH + jg] = hn;              // y2
            if (t == TT - 1)
                out[BB * TT * HH + BB * HH + (b0 + row) * HH + jg] = hn; // hidden layer 1

            uint32_t la = smem_u32(&s->comb[nxt][row][HH + jg]);
            #pragma unroll
            for (int p = 0; p < 8; ++p) st_remote_f32(la, (uint32_t)p, hn);
        }
        CLUSTER_ARRIVE();
    }
    CLUSTER_WAIT();   // exit protection
}

// ================================================================ launch
extern "C" void kernel_launch(void* const* d_in, const int* in_sizes, int n_in,
                              void* d_out, int out_size)
{
    (void)in_sizes; (void)n_in; (void)out_size;
    const float* x   = (const float*)d_in[0];
    const float* Wf1 = (const float*)d_in[1];
    const float* bf1 = (const float*)d_in[2];
    const float* Wc1 = (const float*)d_in[3];
    const float* bc1 = (const float*)d_in[4];
    const float* Wf2 = (const float*)d_in[5];
    const float* bf2 = (const float*)d_in[6];
    const float* Wc2 = (const float*)d_in[7];
    const float* bc2 = (const float*)d_in[8];
    float* out = (float*)d_out;

    cudaFuncSetAttribute(mgu_pass1, cudaFuncAttributeMaxDynamicSharedMemorySize,
                         (int)sizeof(P1Smem));
    cudaFuncSetAttribute(mgu_pass2, cudaFuncAttributeMaxDynamicSharedMemorySize,
                         (int)sizeof(P2Smem));

    mgu_pass1<<<128, 256, sizeof(P1Smem)>>>(x, Wf1, bf1, Wc1, bc1, out);
    mgu_pass2<<<128, 256, sizeof(P2Smem)>>>(Wf2, bf2, Wc2, bc2, out);
}

// round 4
// speedup vs baseline: 2.7963x; 1.3201x over previous
#include <cuda_runtime.h>
#include <cstdint>

#define BB 64
#define TT 1024
#define II 128
#define HH 256

// y1 scratch: [B, T, H] fp32 = 64 MB
__device__ float g_y1[BB * TT * HH];

// ---------------------------------------------------------------- helpers
__device__ __forceinline__ uint32_t smem_u32(const void* p) {
    uint32_t a;
    asm("{ .reg .u64 t; cvta.to.shared.u64 t, %1; cvt.u32.u64 %0, t; }"
        : "=r"(a) : "l"(p));
    return a;
}
__device__ __forceinline__ uint32_t mapa_(uint32_t addr, uint32_t rank) {
    uint32_t ra;
    asm volatile("mapa.shared::cluster.u32 %0, %1, %2;" : "=r"(ra) : "r"(addr), "r"(rank));
    return ra;
}
// Remote SMEM store that signals the target CTA's mbarrier on data arrival.
__device__ __forceinline__ void st_async_f32_(uint32_t dst, float v, uint32_t mbar) {
    asm volatile("st.async.shared::cluster.mbarrier::complete_tx::bytes.b32 [%0], %1, [%2];"
                 :: "r"(dst), "r"(__float_as_uint(v)), "r"(mbar) : "memory");
}
__device__ __forceinline__ void mbar_init_(uint32_t mbar, uint32_t cnt) {
    asm volatile("mbarrier.init.shared.b64 [%0], %1;" :: "r"(mbar), "r"(cnt) : "memory");
}
__device__ __forceinline__ void mbar_expect_tx_(uint32_t mbar, uint32_t bytes) {
    asm volatile("mbarrier.arrive.expect_tx.shared.b64 _, [%0], %1;"
                 :: "r"(mbar), "r"(bytes) : "memory");
}
__device__ __forceinline__ void mbar_wait_(uint32_t mbar, uint32_t parity) {
    asm volatile(
        "{\n\t"
        ".reg .pred P;\n"
        "WL_%=:\n\t"
        "mbarrier.try_wait.parity.acquire.cluster.shared::cta.b64 P, [%0], %1;\n\t"
        "@!P bra WL_%=;\n\t"
        "}" :: "r"(mbar), "r"(parity) : "memory");
}
__device__ __forceinline__ void cluster_sync_() {
    asm volatile("barrier.cluster.arrive.aligned;" ::: "memory");
    asm volatile("barrier.cluster.wait.aligned;" ::: "memory");
}
__device__ __forceinline__ float sigmoid_(float z) {
    return __fdividef(1.0f, 1.0f + __expf(-z));
}
__device__ __forceinline__ float tanh_(float z) {
    return __fdividef(2.0f, 1.0f + __expf(-2.0f * z)) - 1.0f;
}

// ================================================================ PASS 1
// Layer 1: cluster of 4 CTAs, 2 batch rows per cluster.
// CTA owns 64 j-columns (BOTH gates), K = 384 (x:128 | h:256).
// 256 threads = j(64) x ks(4). Thread k-slice: k4 = q*4 + ks, q=0..23.
// Handshake: phase D of step t delivers h(t+1) to peers' comb[(t+1)&1] via
// st.async, completing the peers' mbar[(t+1)&1]. Step t waits mbar[t&1] with
// expect_tx = full h bytes, re-arming right after the wait (race-free: next
// arrivals to that mbar require OUR phase-D stores this step). No rendezvous,
// no L1 flush, wakeup ~60cyc instead of ~490.

#define P1_TX 2048u   // 4 CTAs x 128 threads x 4B

struct P1Smem {
    float4 w4[2][96][64];      // [gate][k4][j] : 196608 B
    float  comb[2][2][384];    // double-buffered [x_t | h] per row : 6144 B
    float4 partial[256];       // (af0, ac0, af1, ac1) : 4096 B
    float  biasf[64];
    float  biasc[64];          // 512 B
    unsigned long long mbar[2];
};

__global__ void __cluster_dims__(4, 1, 1) __launch_bounds__(256, 1)
mgu_pass1(const float* __restrict__ x,
          const float* __restrict__ Wf1, const float* __restrict__ bf1,
          const float* __restrict__ Wc1, const float* __restrict__ bc1,
          float* __restrict__ out)
{
    extern __shared__ char raw[];
    P1Smem* s = reinterpret_cast<P1Smem*>(raw);

    const int tid  = threadIdx.x;
    const int rank = blockIdx.x & 3;
    const int cid  = blockIdx.x >> 2;
    const int b0   = cid * 2;
    const int j    = tid & 63;
    const int ks   = tid >> 6;        // 0..3
    const int j0   = rank * 64;

    const uint32_t mb0 = smem_u32(&s->mbar[0]);
    const uint32_t mb1 = smem_u32(&s->mbar[1]);

    // ---- weights: w4[gate][k>>2][j].comp[k&3]
    for (int idx = tid; idx < 384 * 64; idx += 256) {
        int k = idx >> 6, jj = idx & 63;
        reinterpret_cast<float*>(&s->w4[0][k >> 2][jj])[k & 3] = Wf1[k * HH + j0 + jj];
        reinterpret_cast<float*>(&s->w4[1][k >> 2][jj])[k & 3] = Wc1[k * HH + j0 + jj];
    }
    if (tid < 64) { s->biasf[tid] = bf1[j0 + tid]; s->biasc[tid] = bc1[j0 + tid]; }

    if (tid == 0) {
        mbar_init_(mb0, 1);  mbar_init_(mb1, 1);
        mbar_expect_tx_(mb0, P1_TX);  mbar_expect_tx_(mb1, P1_TX);
    }

    // ---- comb init: zero both buffers, then x(0)
    for (int idx = tid; idx < 2 * 2 * 384; idx += 256)
        reinterpret_cast<float*>(s->comb)[idx] = 0.0f;
    __syncthreads();
    if (tid < 64) {
        int row = tid >> 5, ch = tid & 31;
        reinterpret_cast<float4*>(&s->comb[0][row][0])[ch] =
            reinterpret_cast<const float4*>(&x[(b0 + row) * (TT * II)])[ch];
    }
    __syncthreads();
    cluster_sync_();   // peers' mbarriers + buffers initialized before any st.async

    const int prow = tid >> 5, pch = tid & 31;   // x-prefetch mapping (tid < 64)
    int ph0 = 0, ph1 = 0;

    for (int t = 0; t < TT; ++t) {
        const int cur = t & 1, nxt = cur ^ 1;

        // prefetch x(t+1) (DRAM latency hidden under the dot)
        float4 xv = make_float4(0.f, 0.f, 0.f, 0.f);
        if (tid < 64 && t + 1 < TT)
            xv = *reinterpret_cast<const float4*>(
                &x[(b0 + prow) * (TT * II) + (t + 1) * II + pch * 4]);

        const float4* cb0 = reinterpret_cast<const float4*>(s->comb[cur][0]);
        const float4* cb1 = reinterpret_cast<const float4*>(s->comb[cur][1]);
        float af0 = 0.f, ac0 = 0.f, af1 = 0.f, ac1 = 0.f;

        // ---- A: x-portion (independent of h(t)) — hides the mbar wait
        #pragma unroll
        for (int q = 0; q < 8; ++q) {
            const int k4 = q * 4 + ks;
            float4 w0 = s->w4[0][k4][j];
            float4 w1 = s->w4[1][k4][j];
            float4 v0 = cb0[k4];
            float4 v1 = cb1[k4];
            af0 = fmaf(w0.x, v0.x, af0); af0 = fmaf(w0.y, v0.y, af0);
            af0 = fmaf(w0.z, v0.z, af0); af0 = fmaf(w0.w, v0.w, af0);
            ac0 = fmaf(w1.x, v0.x, ac0); ac0 = fmaf(w1.y, v0.y, ac0);
            ac0 = fmaf(w1.z, v0.z, ac0); ac0 = fmaf(w1.w, v0.w, ac0);
            af1 = fmaf(w0.x, v1.x, af1); af1 = fmaf(w0.y, v1.y, af1);
            af1 = fmaf(w0.z, v1.z, af1); af1 = fmaf(w0.w, v1.w, af1);
            ac1 = fmaf(w1.x, v1.x, ac1); ac1 = fmaf(w1.y, v1.y, ac1);
            ac1 = fmaf(w1.z, v1.z, ac1); ac1 = fmaf(w1.w, v1.w, ac1);
        }

        if (t) {
            if (t & 1) { mbar_wait_(mb1, ph1); ph1 ^= 1; }
            else       { mbar_wait_(mb0, ph0); ph0 ^= 1; }
            if (tid == 0) mbar_expect_tx_((t & 1) ? mb1 : mb0, P1_TX);  // re-arm for t+2
        }

        // ---- B: h-portion
        #pragma unroll
        for (int q = 8; q < 24; ++q) {
            const int k4 = q * 4 + ks;
            float4 w0 = s->w4[0][k4][j];
            float4 w1 = s->w4[1][k4][j];
            float4 v0 = cb0[k4];
            float4 v1 = cb1[k4];
            af0 = fmaf(w0.x, v0.x, af0); af0 = fmaf(w0.y, v0.y, af0);
            af0 = fmaf(w0.z, v0.z, af0); af0 = fmaf(w0.w, v0.w, af0);
            ac0 = fmaf(w1.x, v0.x, ac0); ac0 = fmaf(w1.y, v0.y, ac0);
            ac0 = fmaf(w1.z, v0.z, ac0); ac0 = fmaf(w1.w, v0.w, ac0);
            af1 = fmaf(w0.x, v1.x, af1); af1 = fmaf(w0.y, v1.y, af1);
            af1 = fmaf(w0.z, v1.z, af1); af1 = fmaf(w0.w, v1.w, af1);
            ac1 = fmaf(w1.x, v1.x, ac1); ac1 = fmaf(w1.y, v1.y, ac1);
            ac1 = fmaf(w1.w, v1.w, ac1); ac1 = fmaf(w1.z, v1.z, ac1);
        }

        // stage x(t+1)
        if (tid < 64 && t + 1 < TT)
            reinterpret_cast<float4*>(&s->comb[nxt][prow][0])[pch] = xv;

        s->partial[tid] = make_float4(af0, ac0, af1, ac1);
        __syncthreads();

        // ---- D: reduce + activations + h update + st.async broadcast
        if (tid < 128) {
            const int row = tid >> 6, jl = tid & 63;
            float4 p0 = s->partial[jl];
            float4 p1 = s->partial[64 + jl];
            float4 p2 = s->partial[128 + jl];
            float4 p3 = s->partial[192 + jl];
            float pf, pc;
            if (row == 0) { pf = (p0.x + p1.x) + (p2.x + p3.x);
                            pc = (p0.y + p1.y) + (p2.y + p3.y); }
            else          { pf = (p0.z + p1.z) + (p2.z + p3.z);
                            pc = (p0.w + p1.w) + (p2.w + p3.w); }
            pf += s->biasf[jl];
            pc += s->biasc[jl];
            float f = sigmoid_(pf);
            float c = tanh_(pc);
            const int jg = j0 + jl;
            float hold = s->comb[cur][row][II + jg];
            float hn   = fmaf(f, hold - c, c);     // f*h + (1-f)*c

            // remote delivery first (latency-critical), then global stores
            if (t + 1 < TT) {
                uint32_t la = smem_u32(&s->comb[nxt][row][II + jg]);
                uint32_t lm = ((t + 1) & 1) ? mb1 : mb0;
                #pragma unroll
                for (int p = 0; p < 4; ++p)
                    st_async_f32_(mapa_(la, (uint32_t)p), hn, mapa_(lm, (uint32_t)p));
            }
            g_y1[(b0 + row) * (TT * HH) + t * HH + jg] = hn;
            if (t == TT - 1)
                out[BB * TT * HH + (b0 + row) * HH + jg] = hn;   // hidden layer 0
        }
    }
    cluster_sync_();   // exit insurance
}

// ================================================================ PASS 2
// Layer 2: cluster of 8 CTAs, 4 batch rows per cluster.
// CTA owns 32 j-columns (BOTH gates), K = 512 (y1:256 | h:256).
// 256 threads = j(32) x ks(8). Same handshake, 8 peers.

#define P2_TX 4096u   // 8 CTAs x 128 threads x 4B

struct P2Smem {
    float4 w4[2][128][32];     // 131072 B
    float  comb[2][4][512];    // 16384 B
    float  partial[256][8];    // af[4] | ac[4] : 8192 B
    float  biasf[32];
    float  biasc[32];          // 256 B
    unsigned long long mbar[2];
};

__global__ void __cluster_dims__(8, 1, 1) __launch_bounds__(256, 1)
mgu_pass2(const float* __restrict__ Wf2, const float* __restrict__ bf2,
          const float* __restrict__ Wc2, const float* __restrict__ bc2,
          float* __restrict__ out)
{
    extern __shared__ char raw[];
    P2Smem* s = reinterpret_cast<P2Smem*>(raw);

    const int tid  = threadIdx.x;
    const int rank = blockIdx.x & 7;
    const int cid  = blockIdx.x >> 3;
    const int b0   = cid * 4;
    const int j    = tid & 31;
    const int ks   = tid >> 5;        // 0..7
    const int j0   = rank * 32;

    const uint32_t mb0 = smem_u32(&s->mbar[0]);
    const uint32_t mb1 = smem_u32(&s->mbar[1]);

    // ---- weights
    for (int idx = tid; idx < 512 * 32; idx += 256) {
        int k = idx >> 5, jj = idx & 31;
        reinterpret_cast<float*>(&s->w4[0][k >> 2][jj])[k & 3] = Wf2[k * HH + j0 + jj];
        reinterpret_cast<float*>(&s->w4[1][k >> 2][jj])[k & 3] = Wc2[k * HH + j0 + jj];
    }
    if (tid < 32) { s->biasf[tid] = bf2[j0 + tid]; s->biasc[tid] = bc2[j0 + tid]; }

    if (tid == 0) {
        mbar_init_(mb0, 1);  mbar_init_(mb1, 1);
        mbar_expect_tx_(mb0, P2_TX);  mbar_expect_tx_(mb1, P2_TX);
    }

    for (int idx = tid; idx < 2 * 4 * 512; idx += 256)
        reinterpret_cast<float*>(s->comb)[idx] = 0.0f;
    __syncthreads();
    {
        int row = tid >> 6, ch = tid & 63;    // all 256 threads: 4 rows x 64 float4
        reinterpret_cast<float4*>(&s->comb[0][row][0])[ch] =
            reinterpret_cast<const float4*>(&g_y1[(b0 + row) * (TT * HH)])[ch];
    }
    __syncthreads();
    cluster_sync_();

    const int prow = tid >> 6, pch = tid & 63;
    int ph0 = 0, ph1 = 0;

    for (int t = 0; t < TT; ++t) {
        const int cur = t & 1, nxt = cur ^ 1;

        float4 yv = make_float4(0.f, 0.f, 0.f, 0.f);
        if (t + 1 < TT)
            yv = *reinterpret_cast<const float4*>(
                &g_y1[(b0 + prow) * (TT * HH) + (t + 1) * HH + pch * 4]);

        const float4* cb0 = reinterpret_cast<const float4*>(s->comb[cur][0]);
        const float4* cb1 = reinterpret_cast<const float4*>(s->comb[cur][1]);
        const float4* cb2 = reinterpret_cast<const float4*>(s->comb[cur][2]);
        const float4* cb3 = reinterpret_cast<const float4*>(s->comb[cur][3]);
        float af0 = 0.f, af1 = 0.f, af2 = 0.f, af3 = 0.f;
        float ac0 = 0.f, ac1 = 0.f, ac2 = 0.f, ac3 = 0.f;

        #pragma unroll
        for (int q = 0; q < 8; ++q) {          // A: y1 region
            const int k4 = q * 8 + ks;
            float4 w0 = s->w4[0][k4][j];
            float4 w1 = s->w4[1][k4][j];
            float4 v;
            v = cb0[k4];
            af0 = fmaf(w0.x, v.x, af0); af0 = fmaf(w0.y, v.y, af0);
            af0 = fmaf(w0.z, v.z, af0); af0 = fmaf(w0.w, v.w, af0);
            ac0 = fmaf(w1.x, v.x, ac0); ac0 = fmaf(w1.y, v.y, ac0);
            ac0 = fmaf(w1.z, v.z, ac0); ac0 = fmaf(w1.w, v.w, ac0);
            v = cb1[k4];
            af1 = fmaf(w0.x, v.x, af1); af1 = fmaf(w0.y, v.y, af1);
            af1 = fmaf(w0.z, v.z, af1); af1 = fmaf(w0.w, v.w, af1);
            ac1 = fmaf(w1.x, v.x, ac1); ac1 = fmaf(w1.y, v.y, ac1);
            ac1 = fmaf(w1.z, v.z, ac1); ac1 = fmaf(w1.w, v.w, ac1);
            v = cb2[k4];
            af2 = fmaf(w0.x, v.x, af2); af2 = fmaf(w0.y, v.y, af2);
            af2 = fmaf(w0.z, v.z, af2); af2 = fmaf(w0.w, v.w, af2);
            ac2 = fmaf(w1.x, v.x, ac2); ac2 = fmaf(w1.y, v.y, ac2);
            ac2 = fmaf(w1.z, v.z, ac2); ac2 = fmaf(w1.w, v.w, ac2);
            v = cb3[k4];
            af3 = fmaf(w0.x, v.x, af3); af3 = fmaf(w0.y, v.y, af3);
            af3 = fmaf(w0.z, v.z, af3); af3 = fmaf(w0.w, v.w, af3);
            ac3 = fmaf(w1.x, v.x, ac3); ac3 = fmaf(w1.y, v.y, ac3);
            ac3 = fmaf(w1.z, v.z, ac3); ac3 = fmaf(w1.w, v.w, ac3);
        }

        if (t) {
            if (t & 1) { mbar_wait_(mb1, ph1); ph1 ^= 1; }
            else       { mbar_wait_(mb0, ph0); ph0 ^= 1; }
            if (tid == 0) mbar_expect_tx_((t & 1) ? mb1 : mb0, P2_TX);
        }

        #pragma unroll
        for (int q = 8; q < 16; ++q) {         // B: h region
            const int k4 = q * 8 + ks;
            float4 w0 = s->w4[0][k4][j];
            float4 w1 = s->w4[1][k4][j];
            float4 v;
            v = cb0[k4];
            af0 = fmaf(w0.x, v.x, af0); af0 = fmaf(w0.y, v.y, af0);
            af0 = fmaf(w0.z, v.z, af0); af0 = fmaf(w0.w, v.w, af0);
            ac0 = fmaf(w1.x, v.x, ac0); ac0 = fmaf(w1.y, v.y, ac0);
            ac0 = fmaf(w1.z, v.z, ac0); ac0 = fmaf(w1.w, v.w, ac0);
            v = cb1[k4];
            af1 = fmaf(w0.x, v.x, af1); af1 = fmaf(w0.y, v.y, af1);
            af1 = fmaf(w0.z, v.z, af1); af1 = fmaf(w0.w, v.w, af1);
            ac1 = fmaf(w1.x, v.x, ac1); ac1 = fmaf(w1.y, v.y, ac1);
            ac1 = fmaf(w1.z, v.z, ac1); ac1 = fmaf(w1.w, v.w, ac1);
            v = cb2[k4];
            af2 = fmaf(w0.x, v.x, af2); af2 = fmaf(w0.y, v.y, af2);
            af2 = fmaf(w0.z, v.z, af2); af2 = fmaf(w0.w, v.w, af2);
            ac2 = fmaf(w1.x, v.x, ac2); ac2 = fmaf(w1.y, v.y, ac2);
            ac2 = fmaf(w1.z, v.z, ac2); ac2 = fmaf(w1.w, v.w, ac2);
            v = cb3[k4];
            af3 = fmaf(w0.x, v.x, af3); af3 = fmaf(w0.y, v.y, af3);
            af3 = fmaf(w0.z, v.z, af3); af3 = fmaf(w0.w, v.w, af3);
            ac3 = fmaf(w1.x, v.x, ac3); ac3 = fmaf(w1.y, v.y, ac3);
            ac3 = fmaf(w1.z, v.z, ac3); ac3 = fmaf(w1.w, v.w, ac3);
        }

        if (t + 1 < TT)
            reinterpret_cast<float4*>(&s->comb[nxt][prow][0])[pch] = yv;

        reinterpret_cast<float4*>(s->partial[tid])[0] = make_float4(af0, af1, af2, af3);
        reinterpret_cast<float4*>(s->partial[tid])[1] = make_float4(ac0, ac1, ac2, ac3);
        __syncthreads();

        if (tid < 128) {
            const int row = tid >> 5, jl = tid & 31;
            float pf = s->biasf[jl], pc = s->biasc[jl];
            #pragma unroll
            for (int kk = 0; kk < 8; ++kk) {
                pf += s->partial[kk * 32 + jl][row];
                pc += s->partial[kk * 32 + jl][4 + row];
            }
            float f = sigmoid_(pf);
            float c = tanh_(pc);
            const int jg = j0 + jl;
            float hold = s->comb[cur][row][HH + jg];
            float hn   = fmaf(f, hold - c, c);

            if (t + 1 < TT) {
                uint32_t la = smem_u32(&s->comb[nxt][row][HH + jg]);
                uint32_t lm = ((t + 1) & 1) ? mb1 : mb0;
                #pragma unroll
                for (int p = 0; p < 8; ++p)
                    st_async_f32_(mapa_(la, (uint32_t)p), hn, mapa_(lm, (uint32_t)p));
            }
            out[(b0 + row) * (TT * HH) + t * HH + jg] = hn;              // y2
            if (t == TT - 1)
                out[BB * TT * HH + BB * HH + (b0 + row) * HH + jg] = hn; // hidden layer 1
        }
    }
    cluster_sync_();   // exit insurance
}

// ================================================================ launch
extern "C" void kernel_launch(void* const* d_in, const int* in_sizes, int n_in,
                              void* d_out, int out_size)
{
    (void)in_sizes; (void)n_in; (void)out_size;
    const float* x   = (const float*)d_in[0];
    const float* Wf1 = (const float*)d_in[1];
    const float* bf1 = (const float*)d_in[2];
    const float* Wc1 = (const float*)d_in[3];
    const float* bc1 = (const float*)d_in[4];
    const float* Wf2 = (const float*)d_in[5];
    const float* bf2 = (const float*)d_in[6];
    const float* Wc2 = (const float*)d_in[7];
    const float* bc2 = (const float*)d_in[8];
    float* out = (float*)d_out;

    cudaFuncSetAttribute(mgu_pass1, cudaFuncAttributeMaxDynamicSharedMemorySize,
                         (int)sizeof(P1Smem));
    cudaFuncSetAttribute(mgu_pass2, cudaFuncAttributeMaxDynamicSharedMemorySize,
                         (int)sizeof(P2Smem));

    mgu_pass1<<<128, 256, sizeof(P1Smem)>>>(x, Wf1, bf1, Wc1, bc1, out);
    mgu_pass2<<<128, 256, sizeof(P2Smem)>>>(Wf2, bf2, Wc2, bc2, out);
}

// round 5
// speedup vs baseline: 3.4506x; 1.2340x over previous
#include <cuda_runtime.h>
#include <cstdint>

#define BB 64
#define TT 1024
#define II 128
#define HH 256

// y1 scratch: [B, T, H] fp32 = 64 MB
__device__ float g_y1[BB * TT * HH];

// ---------------------------------------------------------------- helpers
__device__ __forceinline__ uint32_t smem_u32(const void* p) {
    uint32_t a;
    asm("{ .reg .u64 t; cvta.to.shared.u64 t, %1; cvt.u32.u64 %0, t; }"
        : "=r"(a) : "l"(p));
    return a;
}
__device__ __forceinline__ uint32_t mapa_(uint32_t addr, uint32_t rank) {
    uint32_t ra;
    asm volatile("mapa.shared::cluster.u32 %0, %1, %2;" : "=r"(ra) : "r"(addr), "r"(rank));
    return ra;
}
__device__ __forceinline__ void st_async_f32_(uint32_t dst, float v, uint32_t mbar) {
    asm volatile("st.async.shared::cluster.mbarrier::complete_tx::bytes.b32 [%0], %1, [%2];"
                 :: "r"(dst), "r"(__float_as_uint(v)), "r"(mbar) : "memory");
}
__device__ __forceinline__ void mbar_init_(uint32_t mbar, uint32_t cnt) {
    asm volatile("mbarrier.init.shared.b64 [%0], %1;" :: "r"(mbar), "r"(cnt) : "memory");
}
__device__ __forceinline__ void mbar_expect_tx_(uint32_t mbar, uint32_t bytes) {
    asm volatile("mbarrier.arrive.expect_tx.shared.b64 _, [%0], %1;"
                 :: "r"(mbar), "r"(bytes) : "memory");
}
__device__ __forceinline__ void mbar_wait_(uint32_t mbar, uint32_t parity) {
    asm volatile(
        "{\n\t"
        ".reg .pred P;\n"
        "WL_%=:\n\t"
        "mbarrier.try_wait.parity.acquire.cluster.shared::cta.b64 P, [%0], %1;\n\t"
        "@!P bra WL_%=;\n\t"
        "}" :: "r"(mbar), "r"(parity) : "memory");
}
__device__ __forceinline__ void cluster_sync_() {
    asm volatile("barrier.cluster.arrive.aligned;" ::: "memory");
    asm volatile("barrier.cluster.wait.aligned;" ::: "memory");
}
__device__ __forceinline__ float sigmoid_(float z) {
    return __fdividef(1.0f, 1.0f + __expf(-z));
}
__device__ __forceinline__ float tanh_(float z) {
    return __fdividef(2.0f, 1.0f + __expf(-2.0f * z)) - 1.0f;
}

#define FMA16(af, ac, w0, w1, v)                                  \
    af = fmaf((w0).x, (v).x, af); af = fmaf((w0).y, (v).y, af);   \
    af = fmaf((w0).z, (v).z, af); af = fmaf((w0).w, (v).w, af);   \
    ac = fmaf((w1).x, (v).x, ac); ac = fmaf((w1).y, (v).y, ac);   \
    ac = fmaf((w1).z, (v).z, ac); ac = fmaf((w1).w, (v).w, ac);

// ================================================================ PASS 1
// Layer 1: cluster of 4 CTAs, 2 batch rows per cluster.
// CTA owns 64 j-columns (BOTH gates), K = 384 (x:128 | h:256).
// 256 threads = j(64) x ks(4). Thread k-slice: k4 = q*4 + ks, q=0..23.
//   q 0..7  : x region  — REGISTER weights (wf/wc[0..7]),  pre-wait
//   q 8..15 : h region  — REGISTER weights (wf/wc[8..15]), post-wait
//   q 16..23: h region  — SMEM weights w4h,                post-wait
// Register cache kills 2/3 of the per-step weight crossbar traffic (196KB->65KB).

#define P1_TX 2048u   // 4 CTAs x 128 threads x 4B

struct P1Smem {
    float4 w4h[2][32][64];     // weights for k4 in [64,96) : 65536 B
    float  comb[2][2][384];    // double-buffered [x_t | h] per row : 6144 B
    float4 partial[256];       // (af0, ac0, af1, ac1) : 4096 B
    float  biasf[64];
    float  biasc[64];          // 512 B
    unsigned long long mbar[2];
};                             // ~76 KB

__global__ void __cluster_dims__(4, 1, 1) __launch_bounds__(256, 1)
mgu_pass1(const float* __restrict__ x,
          const float* __restrict__ Wf1, const float* __restrict__ bf1,
          const float* __restrict__ Wc1, const float* __restrict__ bc1,
          float* __restrict__ out)
{
    extern __shared__ char raw[];
    P1Smem* s = reinterpret_cast<P1Smem*>(raw);

    const int tid  = threadIdx.x;
    const int rank = blockIdx.x & 3;
    const int cid  = blockIdx.x >> 2;
    const int b0   = cid * 2;
    const int j    = tid & 63;
    const int ks   = tid >> 6;        // 0..3
    const int j0   = rank * 64;
    const int jg_w = j0 + j;

    const uint32_t mb0 = smem_u32(&s->mbar[0]);
    const uint32_t mb1 = smem_u32(&s->mbar[1]);

    // ---- register weights: q = 0..15 (k = 0..255)
    float4 wf[16], wc[16];
    #pragma unroll
    for (int q = 0; q < 16; ++q) {
        const int kb = (q * 4 + ks) * 4;
        wf[q] = make_float4(Wf1[(kb + 0) * HH + jg_w], Wf1[(kb + 1) * HH + jg_w],
                            Wf1[(kb + 2) * HH + jg_w], Wf1[(kb + 3) * HH + jg_w]);
        wc[q] = make_float4(Wc1[(kb + 0) * HH + jg_w], Wc1[(kb + 1) * HH + jg_w],
                            Wc1[(kb + 2) * HH + jg_w], Wc1[(kb + 3) * HH + jg_w]);
    }

    // ---- SMEM weights: k = 256..383 only
    for (int idx = tid; idx < 128 * 64; idx += 256) {
        int kk = idx >> 6, jj = idx & 63;      // kk 0..127 -> k = 256+kk
        int k = 256 + kk;
        reinterpret_cast<float*>(&s->w4h[0][kk >> 2][jj])[kk & 3] = Wf1[k * HH + j0 + jj];
        reinterpret_cast<float*>(&s->w4h[1][kk >> 2][jj])[kk & 3] = Wc1[k * HH + j0 + jj];
    }
    if (tid < 64) { s->biasf[tid] = bf1[j0 + tid]; s->biasc[tid] = bc1[j0 + tid]; }

    if (tid == 0) {
        mbar_init_(mb0, 1);  mbar_init_(mb1, 1);
        mbar_expect_tx_(mb0, P1_TX);  mbar_expect_tx_(mb1, P1_TX);
    }

    // ---- comb init: zero both buffers, then x(0)
    for (int idx = tid; idx < 2 * 2 * 384; idx += 256)
        reinterpret_cast<float*>(s->comb)[idx] = 0.0f;
    __syncthreads();
    if (tid < 64) {
        int row = tid >> 5, ch = tid & 31;
        reinterpret_cast<float4*>(&s->comb[0][row][0])[ch] =
            reinterpret_cast<const float4*>(&x[(b0 + row) * (TT * II)])[ch];
    }
    __syncthreads();
    cluster_sync_();   // peers' mbarriers + buffers ready before any st.async

    const int prow = tid >> 5, pch = tid & 31;   // x-prefetch mapping (tid < 64)
    int ph0 = 0, ph1 = 0;

    for (int t = 0; t < TT; ++t) {
        const int cur = t & 1, nxt = cur ^ 1;

        float4 xv = make_float4(0.f, 0.f, 0.f, 0.f);
        if (tid < 64 && t + 1 < TT)
            xv = *reinterpret_cast<const float4*>(
                &x[(b0 + prow) * (TT * II) + (t + 1) * II + pch * 4]);

        const float4* cb0 = reinterpret_cast<const float4*>(s->comb[cur][0]);
        const float4* cb1 = reinterpret_cast<const float4*>(s->comb[cur][1]);
        float af0 = 0.f, ac0 = 0.f, af1 = 0.f, ac1 = 0.f;

        // ---- A: x-portion, register weights (hides mbar wait)
        #pragma unroll
        for (int q = 0; q < 8; ++q) {
            const int k4 = q * 4 + ks;
            float4 v0 = cb0[k4];
            float4 v1 = cb1[k4];
            FMA16(af0, ac0, wf[q], wc[q], v0)
            FMA16(af1, ac1, wf[q], wc[q], v1)
        }

        if (t) {
            if (t & 1) { mbar_wait_(mb1, ph1); ph1 ^= 1; }
            else       { mbar_wait_(mb0, ph0); ph0 ^= 1; }
            if (tid == 0) mbar_expect_tx_((t & 1) ? mb1 : mb0, P1_TX);  // re-arm for t+2
        }

        // ---- B1: h-portion, register weights
        #pragma unroll
        for (int q = 8; q < 16; ++q) {
            const int k4 = q * 4 + ks;
            float4 v0 = cb0[k4];
            float4 v1 = cb1[k4];
            FMA16(af0, ac0, wf[q], wc[q], v0)
            FMA16(af1, ac1, wf[q], wc[q], v1)
        }
        // ---- B2: h-portion tail, SMEM weights (k4 64..95)
        #pragma unroll
        for (int q = 0; q < 8; ++q) {
            const int k4 = 64 + q * 4 + ks;
            float4 w0 = s->w4h[0][k4 - 64][j];
            float4 w1 = s->w4h[1][k4 - 64][j];
            float4 v0 = cb0[k4];
            float4 v1 = cb1[k4];
            FMA16(af0, ac0, w0, w1, v0)
            FMA16(af1, ac1, w0, w1, v1)
        }

        // stage x(t+1)
        if (tid < 64 && t + 1 < TT)
            reinterpret_cast<float4*>(&s->comb[nxt][prow][0])[pch] = xv;

        s->partial[tid] = make_float4(af0, ac0, af1, ac1);
        __syncthreads();

        // ---- D: reduce + activations + h update + st.async broadcast
        if (tid < 128) {
            const int row = tid >> 6, jl = tid & 63;
            float4 p0 = s->partial[jl];
            float4 p1 = s->partial[64 + jl];
            float4 p2 = s->partial[128 + jl];
            float4 p3 = s->partial[192 + jl];
            float pf, pc;
            if (row == 0) { pf = (p0.x + p1.x) + (p2.x + p3.x);
                            pc = (p0.y + p1.y) + (p2.y + p3.y); }
            else          { pf = (p0.z + p1.z) + (p2.z + p3.z);
                            pc = (p0.w + p1.w) + (p2.w + p3.w); }
            pf += s->biasf[jl];
            pc += s->biasc[jl];
            float f = sigmoid_(pf);
            float c = tanh_(pc);
            const int jg = j0 + jl;
            float hold = s->comb[cur][row][II + jg];
            float hn   = fmaf(f, hold - c, c);     // f*h + (1-f)*c

            if (t + 1 < TT) {
                uint32_t la = smem_u32(&s->comb[nxt][row][II + jg]);
                uint32_t lm = ((t + 1) & 1) ? mb1 : mb0;
                #pragma unroll
                for (int p = 0; p < 4; ++p)
                    st_async_f32_(mapa_(la, (uint32_t)p), hn, mapa_(lm, (uint32_t)p));
            }
            g_y1[(b0 + row) * (TT * HH) + t * HH + jg] = hn;
            if (t == TT - 1)
                out[BB * TT * HH + (b0 + row) * HH + jg] = hn;   // hidden layer 0
        }
    }
    cluster_sync_();   // exit insurance
}

// ================================================================ PASS 2
// Layer 2: cluster of 8 CTAs, 4 batch rows per cluster.
// CTA owns 32 j-columns (BOTH gates), K = 512 (y1:256 | h:256).
// 256 threads = j(32) x ks(8). ALL weights register-resident (128 regs):
// zero weight SMEM traffic.

#define P2_TX 4096u   // 8 CTAs x 128 threads x 4B

struct P2Smem {
    float  comb[2][4][512];    // 16384 B
    float  partial[256][8];    // af[4] | ac[4] : 8192 B
    float  biasf[32];
    float  biasc[32];          // 256 B
    unsigned long long mbar[2];
};                             // ~25 KB

__global__ void __cluster_dims__(8, 1, 1) __launch_bounds__(256, 1)
mgu_pass2(const float* __restrict__ Wf2, const float* __restrict__ bf2,
          const float* __restrict__ Wc2, const float* __restrict__ bc2,
          float* __restrict__ out)
{
    extern __shared__ char raw[];
    P2Smem* s = reinterpret_cast<P2Smem*>(raw);

    const int tid  = threadIdx.x;
    const int rank = blockIdx.x & 7;
    const int cid  = blockIdx.x >> 3;
    const int b0   = cid * 4;
    const int j    = tid & 31;
    const int ks   = tid >> 5;        // 0..7
    const int j0   = rank * 32;
    const int jg_w = j0 + j;

    const uint32_t mb0 = smem_u32(&s->mbar[0]);
    const uint32_t mb1 = smem_u32(&s->mbar[1]);

    // ---- ALL weights into registers: q = 0..15, k4 = q*8+ks
    float4 wf[16], wc[16];
    #pragma unroll
    for (int q = 0; q < 16; ++q) {
        const int kb = (q * 8 + ks) * 4;
        wf[q] = make_float4(Wf2[(kb + 0) * HH + jg_w], Wf2[(kb + 1) * HH + jg_w],
                            Wf2[(kb + 2) * HH + jg_w], Wf2[(kb + 3) * HH + jg_w]);
        wc[q] = make_float4(Wc2[(kb + 0) * HH + jg_w], Wc2[(kb + 1) * HH + jg_w],
                            Wc2[(kb + 2) * HH + jg_w], Wc2[(kb + 3) * HH + jg_w]);
    }
    if (tid < 32) { s->biasf[tid] = bf2[j0 + tid]; s->biasc[tid] = bc2[j0 + tid]; }

    if (tid == 0) {
        mbar_init_(mb0, 1);  mbar_init_(mb1, 1);
        mbar_expect_tx_(mb0, P2_TX);  mbar_expect_tx_(mb1, P2_TX);
    }

    for (int idx = tid; idx < 2 * 4 * 512; idx += 256)
        reinterpret_cast<float*>(s->comb)[idx] = 0.0f;
    __syncthreads();
    {
        int row = tid >> 6, ch = tid & 63;    // 4 rows x 64 float4
        reinterpret_cast<float4*>(&s->comb[0][row][0])[ch] =
            reinterpret_cast<const float4*>(&g_y1[(b0 + row) * (TT * HH)])[ch];
    }
    __syncthreads();
    cluster_sync_();

    const int prow = tid >> 6, pch = tid & 63;
    int ph0 = 0, ph1 = 0;

    for (int t = 0; t < TT; ++t) {
        const int cur = t & 1, nxt = cur ^ 1;

        float4 yv = make_float4(0.f, 0.f, 0.f, 0.f);
        if (t + 1 < TT)
            yv = *reinterpret_cast<const float4*>(
                &g_y1[(b0 + prow) * (TT * HH) + (t + 1) * HH + pch * 4]);

        const float4* cb0 = reinterpret_cast<const float4*>(s->comb[cur][0]);
        const float4* cb1 = reinterpret_cast<const float4*>(s->comb[cur][1]);
        const float4* cb2 = reinterpret_cast<const float4*>(s->comb[cur][2]);
        const float4* cb3 = reinterpret_cast<const float4*>(s->comb[cur][3]);
        float af0 = 0.f, af1 = 0.f, af2 = 0.f, af3 = 0.f;
        float ac0 = 0.f, ac1 = 0.f, ac2 = 0.f, ac3 = 0.f;

        #pragma unroll
        for (int q = 0; q < 8; ++q) {          // A: y1 region (register weights)
            const int k4 = q * 8 + ks;
            float4 v;
            v = cb0[k4]; FMA16(af0, ac0, wf[q], wc[q], v)
            v = cb1[k4]; FMA16(af1, ac1, wf[q], wc[q], v)
            v = cb2[k4]; FMA16(af2, ac2, wf[q], wc[q], v)
            v = cb3[k4]; FMA16(af3, ac3, wf[q], wc[q], v)
        }

        if (t) {
            if (t & 1) { mbar_wait_(mb1, ph1); ph1 ^= 1; }
            else       { mbar_wait_(mb0, ph0); ph0 ^= 1; }
            if (tid == 0) mbar_expect_tx_((t & 1) ? mb1 : mb0, P2_TX);
        }

        #pragma unroll
        for (int q = 8; q < 16; ++q) {         // B: h region (register weights)
            const int k4 = q * 8 + ks;
            float4 v;
            v = cb0[k4]; FMA16(af0, ac0, wf[q], wc[q], v)
            v = cb1[k4]; FMA16(af1, ac1, wf[q], wc[q], v)
            v = cb2[k4]; FMA16(af2, ac2, wf[q], wc[q], v)
            v = cb3[k4]; FMA16(af3, ac3, wf[q], wc[q], v)
        }

        if (t + 1 < TT)
            reinterpret_cast<float4*>(&s->comb[nxt][prow][0])[pch] = yv;

        reinterpret_cast<float4*>(s->partial[tid])[0] = make_float4(af0, af1, af2, af3);
        reinterpret_cast<float4*>(s->partial[tid])[1] = make_float4(ac0, ac1, ac2, ac3);
        __syncthreads();

        if (tid < 128) {
            const int row = tid >> 5, jl = tid & 31;
            float pf = s->biasf[jl], pc = s->biasc[jl];
            #pragma unroll
            for (int kk = 0; kk < 8; ++kk) {
                pf += s->partial[kk * 32 + jl][row];
                pc += s->partial[kk * 32 + jl][4 + row];
            }
            float f = sigmoid_(pf);
            float c = tanh_(pc);
            const int jg = j0 + jl;
            float hold = s->comb[cur][row][HH + jg];
            float hn   = fmaf(f, hold - c, c);

            if (t + 1 < TT) {
                uint32_t la = smem_u32(&s->comb[nxt][row][HH + jg]);
                uint32_t lm = ((t + 1) & 1) ? mb1 : mb0;
                #pragma unroll
                for (int p = 0; p < 8; ++p)
                    st_async_f32_(mapa_(la, (uint32_t)p), hn, mapa_(lm, (uint32_t)p));
            }
            out[(b0 + row) * (TT * HH) + t * HH + jg] = hn;              // y2
            if (t == TT - 1)
                out[BB * TT * HH + BB * HH + (b0 + row) * HH + jg] = hn; // hidden layer 1
        }
    }
    cluster_sync_();   // exit insurance
}

// ================================================================ launch
extern "C" void kernel_launch(void* const* d_in, const int* in_sizes, int n_in,
                              void* d_out, int out_size)
{
    (void)in_sizes; (void)n_in; (void)out_size;
    const float* x   = (const float*)d_in[0];
    const float* Wf1 = (const float*)d_in[1];
    const float* bf1 = (const float*)d_in[2];
    const float* Wc1 = (const float*)d_in[3];
    const float* bc1 = (const float*)d_in[4];
    const float* Wf2 = (const float*)d_in[5];
    const float* bf2 = (const float*)d_in[6];
    const float* Wc2 = (const float*)d_in[7];
    const float* bc2 = (const float*)d_in[8];
    float* out = (float*)d_out;

    cudaFuncSetAttribute(mgu_pass1, cudaFuncAttributeMaxDynamicSharedMemorySize,
                         (int)sizeof(P1Smem));
    cudaFuncSetAttribute(mgu_pass2, cudaFuncAttributeMaxDynamicSharedMemorySize,
                         (int)sizeof(P2Smem));

    mgu_pass1<<<128, 256, sizeof(P1Smem)>>>(x, Wf1, bf1, Wc1, bc1, out);
    mgu_pass2<<<128, 256, sizeof(P2Smem)>>>(Wf2, bf2, Wc2, bc2, out);
}